// round 1
// baseline (speedup 1.0000x reference)
#include <cuda_runtime.h>
#include <cuda_bf16.h>
#include <math.h>

// Problem constants (fixed by the reference)
#define NN   50000
#define EE   800000
#define NIN  300
#define HH   4
#define CC   64
#define HC   256      // H*C
#define GG   256
#define NOUT 768

// ---------------- scratch (device globals; no allocs allowed) ----------------
__device__ float g_h[(size_t)NN * HC];        // node features after lin   (51.2 MB)
__device__ float g_asrc[NN * HH];
__device__ float g_adst[NN * HH];
__device__ int   g_deg[NN];
__device__ int   g_offs[NN + 1];
__device__ int   g_cursor[NN];
__device__ int   g_csr_src[EE];
__device__ float g_pool[GG * HC];
__device__ float g_cnt[GG];
__device__ int   g_bsum[64];
__device__ int   g_bpref[64];

__device__ __forceinline__ float lrelu(float x, float s) { return x > 0.f ? x : s * x; }

// ---------------- 0: zero scratch ----------------
__global__ void zero_kernel(int n_nodes) {
    int i = blockIdx.x * blockDim.x + threadIdx.x;
    if (i < n_nodes) g_deg[i] = 0;
    if (i < GG * HC) g_pool[i] = 0.f;
    if (i < GG)      g_cnt[i] = 0.f;
}

// ---------------- 1: h = x @ lin_w  (M x 300 @ 300 x 256, fp32) ----------------
#define GBM 64
#define GBN 64
#define GBK 16
__global__ void __launch_bounds__(256) gemm_h_kernel(const float* __restrict__ X,
                                                     const float* __restrict__ W,
                                                     int M) {
    __shared__ float As[GBM][GBK + 1];
    __shared__ float Bs[GBK][GBN + 1];
    int tid = threadIdx.x;
    int tx = tid & 15, ty = tid >> 4;
    int m0 = blockIdx.x * GBM;
    int n0 = blockIdx.y * GBN;
    float acc[4][4];
#pragma unroll
    for (int i = 0; i < 4; i++)
#pragma unroll
        for (int j = 0; j < 4; j++) acc[i][j] = 0.f;

    for (int k0 = 0; k0 < NIN; k0 += GBK) {
#pragma unroll
        for (int i = 0; i < 4; i++) {
            int idx = tid + i * 256;
            int r = idx >> 4, c = idx & 15;
            int gm = m0 + r, gk = k0 + c;
            As[r][c] = (gm < M && gk < NIN) ? X[(size_t)gm * NIN + gk] : 0.f;
        }
#pragma unroll
        for (int i = 0; i < 4; i++) {
            int idx = tid + i * 256;
            int r = idx >> 6, c = idx & 63;
            int gk = k0 + r;
            Bs[r][c] = (gk < NIN) ? W[(size_t)gk * HC + n0 + c] : 0.f;
        }
        __syncthreads();
#pragma unroll
        for (int k = 0; k < GBK; k++) {
            float a[4], b[4];
#pragma unroll
            for (int i = 0; i < 4; i++) a[i] = As[ty * 4 + i][k];
#pragma unroll
            for (int j = 0; j < 4; j++) b[j] = Bs[k][tx * 4 + j];
#pragma unroll
            for (int i = 0; i < 4; i++)
#pragma unroll
                for (int j = 0; j < 4; j++) acc[i][j] += a[i] * b[j];
        }
        __syncthreads();
    }
#pragma unroll
    for (int i = 0; i < 4; i++) {
        int gm = m0 + ty * 4 + i;
        if (gm < M) {
#pragma unroll
            for (int j = 0; j < 4; j++)
                g_h[(size_t)gm * HC + n0 + tx * 4 + j] = acc[i][j];
        }
    }
}

// ---------------- 2: per-node attention logits ----------------
__global__ void att_kernel(const float* __restrict__ att_src,
                           const float* __restrict__ att_dst, int n_nodes) {
    int t = blockIdx.x * blockDim.x + threadIdx.x;   // = n*4 + hd
    if (t >= n_nodes * HH) return;
    int hd = t & 3;
    const float4* hr = (const float4*)(g_h + (size_t)(t >> 2) * HC + hd * CC);
    const float4* ws = (const float4*)(att_src + hd * CC);
    const float4* wd = (const float4*)(att_dst + hd * CC);
    float s1 = 0.f, s2 = 0.f;
#pragma unroll
    for (int c = 0; c < CC / 4; c++) {
        float4 v = hr[c], a = ws[c], b = wd[c];
        s1 += v.x * a.x + v.y * a.y + v.z * a.z + v.w * a.w;
        s2 += v.x * b.x + v.y * b.y + v.z * b.z + v.w * b.w;
    }
    g_asrc[t] = s1;
    g_adst[t] = s2;
}

// ---------------- 3: degree histogram by dst ----------------
__global__ void deg_kernel(const int* __restrict__ dst, int E) {
    int i = blockIdx.x * blockDim.x + threadIdx.x;
    if (i < E) atomicAdd(&g_deg[dst[i]], 1);
}

__global__ void cnt_kernel(const int* __restrict__ batch, int n_nodes) {
    int i = blockIdx.x * blockDim.x + threadIdx.x;
    if (i < n_nodes) atomicAdd(&g_cnt[batch[i]], 1.f);
}

// ---------------- 4: exclusive scan of degrees ----------------
__global__ void scan1_kernel(int n_nodes) {
    __shared__ int s[1024];
    int t = threadIdx.x;
    int gid = blockIdx.x * 1024 + t;
    int v = (gid < n_nodes) ? g_deg[gid] : 0;
    s[t] = v;
    __syncthreads();
    for (int d = 1; d < 1024; d <<= 1) {
        int x = (t >= d) ? s[t - d] : 0;
        __syncthreads();
        s[t] += x;
        __syncthreads();
    }
    if (gid < n_nodes) g_offs[gid] = s[t] - v;       // exclusive within block
    if (t == 1023) g_bsum[blockIdx.x] = s[1023];
}

__global__ void scan2_kernel(int nb) {
    int acc = 0;
    for (int i = 0; i < nb; i++) { int v = g_bsum[i]; g_bpref[i] = acc; acc += v; }
}

__global__ void scan3_kernel(int n_nodes, int E) {
    int gid = blockIdx.x * 1024 + threadIdx.x;
    if (gid < n_nodes) {
        int v = g_offs[gid] + g_bpref[blockIdx.x];
        g_offs[gid] = v;
        g_cursor[gid] = v;
    }
    if (gid == 0) g_offs[n_nodes] = E;
}

// ---------------- 5: scatter src ids into CSR ----------------
__global__ void scatter_kernel(const int* __restrict__ src,
                               const int* __restrict__ dst, int E) {
    int i = blockIdx.x * blockDim.x + threadIdx.x;
    if (i < E) {
        int d = dst[i];
        int pos = atomicAdd(&g_cursor[d], 1);
        g_csr_src[pos] = src[i];
    }
}

// ---------------- 6: fused softmax + aggregate + act + pool (warp/node) -------
__global__ void __launch_bounds__(256) aggregate_kernel(const int* __restrict__ batch,
                                                        const float* __restrict__ bias,
                                                        int n_nodes) {
    int warp_id = (blockIdx.x * blockDim.x + threadIdx.x) >> 5;
    int lane = threadIdx.x & 31;
    if (warp_id >= n_nodes) return;
    int d = warp_id;
    int hd = lane >> 3;   // lane handles columns [lane*8, lane*8+8) -> head lane/8

    float ad_d = g_adst[d * HH + hd];
    float as_d = g_asrc[d * HH + hd];
    float e_self = lrelu(as_d + ad_d, 0.2f);
    int beg = g_offs[d], end = g_offs[d + 1];

    // pass 1: segment max
    float m = e_self;
    for (int k = beg; k < end; k++) {
        int s = g_csr_src[k];
        float e = lrelu(g_asrc[s * HH + hd] + ad_d, 0.2f);
        m = fmaxf(m, e);
    }
    // pass 2: denom
    float den = __expf(e_self - m);
    for (int k = beg; k < end; k++) {
        int s = g_csr_src[k];
        float e = lrelu(g_asrc[s * HH + hd] + ad_d, 0.2f);
        den += __expf(e - m);
    }
    float inv = 1.f / den;

    // pass 3: weighted aggregate
    float a_self = __expf(e_self - m) * inv;
    const float4* hd_row = (const float4*)(g_h + (size_t)d * HC + lane * 8);
    float4 v0 = hd_row[0], v1 = hd_row[1];
    float4 acc0, acc1;
    acc0.x = v0.x * a_self; acc0.y = v0.y * a_self; acc0.z = v0.z * a_self; acc0.w = v0.w * a_self;
    acc1.x = v1.x * a_self; acc1.y = v1.y * a_self; acc1.z = v1.z * a_self; acc1.w = v1.w * a_self;

    for (int k = beg; k < end; k++) {
        int s = g_csr_src[k];
        float e = lrelu(g_asrc[s * HH + hd] + ad_d, 0.2f);
        float a = __expf(e - m) * inv;
        const float4* hs = (const float4*)(g_h + (size_t)s * HC + lane * 8);
        float4 w0 = hs[0], w1 = hs[1];
        acc0.x += a * w0.x; acc0.y += a * w0.y; acc0.z += a * w0.z; acc0.w += a * w0.w;
        acc1.x += a * w1.x; acc1.y += a * w1.y; acc1.z += a * w1.z; acc1.w += a * w1.w;
    }

    // epilogue: bias + leaky(0.01) + pool atomicAdd
    int g = batch[d];
    float* p = g_pool + g * HC + lane * 8;
    const float* b = bias + lane * 8;
    float vals[8] = {acc0.x, acc0.y, acc0.z, acc0.w, acc1.x, acc1.y, acc1.z, acc1.w};
#pragma unroll
    for (int j = 0; j < 8; j++) {
        float v = lrelu(vals[j] + b[j], 0.01f);
        atomicAdd(&p[j], v);
    }
}

// ---------------- 7: pooled @ fc1_w + fc1_b ----------------
__global__ void __launch_bounds__(256) final_gemm_kernel(const float* __restrict__ fc1_w,
                                                         const float* __restrict__ fc1_b,
                                                         float* __restrict__ out) {
    int g = blockIdx.y;
    int o = blockIdx.x * 256 + threadIdx.x;
    __shared__ float prow[HC];
    float ic = 1.f / fmaxf(g_cnt[g], 1.f);
    prow[threadIdx.x] = g_pool[g * HC + threadIdx.x] * ic;
    __syncthreads();
    float sum = fc1_b[o];
#pragma unroll 8
    for (int k = 0; k < HC; k++) sum += prow[k] * fc1_w[k * NOUT + o];
    out[g * NOUT + o] = sum;
}

// ---------------- launch ----------------
extern "C" void kernel_launch(void* const* d_in, const int* in_sizes, int n_in,
                              void* d_out, int out_size) {
    const float* x       = (const float*)d_in[0];
    const int*   ei      = (const int*)d_in[1];
    const int*   batch   = (const int*)d_in[2];
    const float* lin_w   = (const float*)d_in[3];
    const float* att_src = (const float*)d_in[4];
    const float* att_dst = (const float*)d_in[5];
    const float* bias    = (const float*)d_in[6];
    const float* fc1_w   = (const float*)d_in[7];
    const float* fc1_b   = (const float*)d_in[8];
    float* out = (float*)d_out;

    int n_nodes = in_sizes[2];        // 50000
    int E = in_sizes[1] / 2;          // 800000
    const int* src = ei;
    const int* dst = ei + E;

    int zero_n = (n_nodes > GG * HC) ? n_nodes : GG * HC;
    zero_kernel<<<(zero_n + 255) / 256, 256>>>(n_nodes);

    dim3 gg((n_nodes + GBM - 1) / GBM, HC / GBN);
    gemm_h_kernel<<<gg, 256>>>(x, lin_w, n_nodes);

    att_kernel<<<(n_nodes * HH + 127) / 128, 128>>>(att_src, att_dst, n_nodes);

    deg_kernel<<<(E + 255) / 256, 256>>>(dst, E);
    cnt_kernel<<<(n_nodes + 255) / 256, 256>>>(batch, n_nodes);

    int nb = (n_nodes + 1023) / 1024;
    scan1_kernel<<<nb, 1024>>>(n_nodes);
    scan2_kernel<<<1, 1>>>(nb);
    scan3_kernel<<<nb, 1024>>>(n_nodes, E);

    scatter_kernel<<<(E + 255) / 256, 256>>>(src, dst, E);

    aggregate_kernel<<<(n_nodes * 32 + 255) / 256, 256>>>(batch, bias, n_nodes);

    dim3 fg(NOUT / 256, GG);
    final_gemm_kernel<<<fg, 256>>>(fc1_w, fc1_b, out);
}